// round 1
// baseline (speedup 1.0000x reference)
#include <cuda_runtime.h>

// YOLOv1 loss: [B,7,7,30] x2 f32 -> scalar. HBM-bound reduction (~193 MB).
// Strategy: coalesced float4 loads -> padded smem scatter (stride 31, bank-
// conflict-free reads) -> thread-per-cell compute -> warp/block reduce ->
// double atomicAdd -> finalize divides by batch.

#define TPB    128
#define CPB    128   // cells per block (== TPB, one cell per thread)
#define DIM    30
#define PADDIM 31
#define EPSF   1e-6f

__device__ double g_acc;

__global__ void zero_kernel() { g_acc = 0.0; }

__global__ void finalize_kernel(float* __restrict__ out, double inv_batch) {
    out[0] = (float)(g_acc * inv_batch);
}

__device__ __forceinline__ float sq(float x) { return x * x; }

__device__ __forceinline__ float iou_yolo(const float* __restrict__ a,
                                          const float* __restrict__ b) {
    float ax1 = a[0] - 0.5f * a[2], ax2 = a[0] + 0.5f * a[2];
    float ay1 = a[1] - 0.5f * a[3], ay2 = a[1] + 0.5f * a[3];
    float bx1 = b[0] - 0.5f * b[2], bx2 = b[0] + 0.5f * b[2];
    float by1 = b[1] - 0.5f * b[3], by2 = b[1] + 0.5f * b[3];
    float iw = fmaxf(fminf(ax2, bx2) - fmaxf(ax1, bx1), 0.0f);
    float ih = fmaxf(fminf(ay2, by2) - fmaxf(ay1, by1), 0.0f);
    float inter = iw * ih;
    float a1 = fabsf((ax2 - ax1) * (ay2 - ay1));
    float a2 = fabsf((bx2 - bx1) * (by2 - by1));
    return inter / (a1 + a2 - inter + EPSF);
}

__global__ void __launch_bounds__(TPB)
yolo_loss_kernel(const float* __restrict__ yt_g,
                 const float* __restrict__ yp_g,
                 long long n_cells) {
    __shared__ float st[CPB * PADDIM];
    __shared__ float sp[CPB * PADDIM];

    long long base = (long long)blockIdx.x * CPB;
    int cells = (int)min((long long)CPB, n_cells - base);
    int nflt  = cells * DIM;

    const float* yt = yt_g + base * DIM;
    const float* yp = yp_g + base * DIM;

    // Coalesced float4 loads, scatter into padded smem.
    // base*DIM*4 = blockIdx*15360 bytes -> 16B aligned. Full blocks have
    // nflt = 3840 (divisible by 4); tail loop covers a ragged last block.
    int nv4 = nflt >> 2;
    const float4* yt4 = (const float4*)yt;
    const float4* yp4 = (const float4*)yp;
    for (int j = threadIdx.x; j < nv4; j += TPB) {
        float4 t4 = yt4[j];
        float4 p4 = yp4[j];
        float tv[4] = {t4.x, t4.y, t4.z, t4.w};
        float pv[4] = {p4.x, p4.y, p4.z, p4.w};
        int f = 4 * j;
#pragma unroll
        for (int k = 0; k < 4; k++) {
            int idx = f + k;
            int c = idx / DIM;
            int e = idx - c * DIM;
            st[c * PADDIM + e] = tv[k];
            sp[c * PADDIM + e] = pv[k];
        }
    }
    for (int j = (nv4 << 2) + threadIdx.x; j < nflt; j += TPB) {
        int c = j / DIM;
        int e = j - c * DIM;
        st[c * PADDIM + e] = yt[j];
        sp[c * PADDIM + e] = yp[j];
    }
    __syncthreads();

    float per = 0.0f;
    if (threadIdx.x < cells) {
        const float* t = st + threadIdx.x * PADDIM;
        const float* p = sp + threadIdx.x * PADDIM;

        float obj = (t[4] == 1.0f) ? 1.0f : 0.0f;

        float iou1 = iou_yolo(t, p);
        float iou2 = iou_yolo(t, p + 5);
        bool best1 = iou1 > iou2;

        const float* bh = best1 ? p : (p + 5);
        float conf_hat  = best1 ? p[4] : p[9];
        float other_hat = best1 ? p[9] : p[4];

        float xy = sq(t[0] - bh[0]) + sq(t[1] - bh[1]);
        float wh = sq(sqrtf(t[2]) - sqrtf(fabsf(bh[2] + EPSF)))
                 + sq(sqrtf(t[3]) - sqrtf(fabsf(bh[3] + EPSF)));
        float obj_conf     = sq(t[4] - conf_hat);
        float noobj_in_obj = 0.5f * other_hat * other_hat;
        float noobj_cells  = 0.5f * (sq(t[4] - p[4]) + sq(t[4] - p[9]));

        float cls = 0.0f;
#pragma unroll
        for (int k = 0; k < 20; k++) cls += sq(t[10 + k] - p[10 + k]);

        per = obj * (5.0f * (xy + wh) + obj_conf + noobj_in_obj + cls)
            + (1.0f - obj) * noobj_cells;
    }

    // Warp reduce.
#pragma unroll
    for (int o = 16; o > 0; o >>= 1)
        per += __shfl_xor_sync(0xFFFFFFFFu, per, o);

    __shared__ float wsum[TPB / 32];
    int lane = threadIdx.x & 31;
    int warp = threadIdx.x >> 5;
    if (lane == 0) wsum[warp] = per;
    __syncthreads();

    if (threadIdx.x == 0) {
        float s = 0.0f;
#pragma unroll
        for (int i = 0; i < TPB / 32; i++) s += wsum[i];
        atomicAdd(&g_acc, (double)s);
    }
}

extern "C" void kernel_launch(void* const* d_in, const int* in_sizes, int n_in,
                              void* d_out, int out_size) {
    const float* yt = (const float*)d_in[0];   // y_trues
    const float* yp = (const float*)d_in[1];   // y_preds
    long long n_cells = (long long)in_sizes[0] / DIM;     // batch * 49
    long long batch   = n_cells / 49;
    int blocks = (int)((n_cells + CPB - 1) / CPB);

    zero_kernel<<<1, 1>>>();
    yolo_loss_kernel<<<blocks, TPB>>>(yt, yp, n_cells);
    finalize_kernel<<<1, 1>>>((float*)d_out, 1.0 / (double)batch);
}